// round 10
// baseline (speedup 1.0000x reference)
#include <cuda_runtime.h>
#include <math.h>

#define RR 16
#define GG 4096
#define KN 8
#define HID 64
#define BATCH 4
#define NPTS 4096
#define NBIN 4096   // 16^3 bins per batch

typedef unsigned long long u64;

// ---------------- device scratch (no allocations allowed) ----------------
__device__ int    g_knn[BATCH * GG * KN];
__device__ float  g_vol[BATCH * HID * GG];
__device__ float  g_t1[BATCH * HID * GG];
__device__ float  g_t2[BATCH * HID * GG];
__device__ float  g_vol2[BATCH * HID * 512];
__device__ float  g_ps[64 * HID];
__device__ float  g_pq[64 * HID];
__device__ float  g_sum_bc[BATCH * HID];
__device__ float  g_ssq_bc[BATCH * HID];
// KNN binning
__device__ int    g_bcnt[BATCH * NBIN];
__device__ int    g_boff[BATCH * NBIN + 1];
__device__ int    g_bcur[BATCH * NBIN];
__device__ float4 g_pts[BATCH * NPTS];   // x,y,z,pn  (CSR order)
__device__ int    g_pidx[BATCH * NPTS];  // point index within batch

// ---------------- packed fp32x2 helpers (sm_103a FFMA2) ----------------
__device__ __forceinline__ void ffma2(u64& d, u64 a, u64 b) {
    asm("fma.rn.f32x2 %0, %1, %2, %0;" : "+l"(d) : "l"(a), "l"(b));
}
__device__ __forceinline__ u64 pack2(float lo, float hi) {
    u64 r; asm("mov.b64 %0, {%1, %2};" : "=l"(r) : "f"(lo), "f"(hi)); return r;
}
__device__ __forceinline__ void unpack2(float& lo, float& hi, u64 v) {
    asm("mov.b64 {%0, %1}, %2;" : "=f"(lo), "=f"(hi) : "l"(v));
}

__device__ __forceinline__ float gelu_f(float v) {
    float a = 0.7978845608028654f * (v + 0.044715f * v * v * v);
    float t = 1.0f - __fdividef(2.0f, __expf(2.0f * a) + 1.0f);
    return 0.5f * v * (1.0f + t);
}

// linspace(-1,1,16) bit-exact: rn(-1 + rn(i * rn(2/15)))
__device__ __forceinline__ float grid_coord(int i) {
    const float delta = 2.0f / 15.0f;
    return __fadd_rn(-1.0f, __fmul_rn((float)i, delta));
}

__device__ __forceinline__ int bin_of(float v) {
    int q = (int)floorf((v + 1.0f) * 8.0f);
    return min(15, max(0, q));
}

// ---------------- binning: count / scan / scatter ----------------
__global__ void bin_count(const float* __restrict__ pos) {
    int i = blockIdx.x * 256 + threadIdx.x;           // 16384 points
    int b = i >> 12, n = i & 4095;
    const float* p = pos + (b * NPTS + n) * 3;
    int bx = bin_of(p[0]), by = bin_of(p[1]), bz = bin_of(p[2]);
    atomicAdd(&g_bcnt[b * NBIN + (bx * 16 + by) * 16 + bz], 1);
}

__global__ void bin_scan() {   // 1 block, 256 threads, 16384 bins
    __shared__ int ssum[256];
    __shared__ int spre[256];
    int t = threadIdx.x;
    int base = t * 64;
    int s = 0;
    for (int k = 0; k < 64; k++) s += g_bcnt[base + k];
    ssum[t] = s;
    __syncthreads();
    if (t == 0) {
        int acc = 0;
        for (int k = 0; k < 256; k++) { spre[k] = acc; acc += ssum[k]; }
    }
    __syncthreads();
    int acc = spre[t];
    for (int k = 0; k < 64; k++) {
        int c = g_bcnt[base + k];
        g_boff[base + k] = acc;
        g_bcur[base + k] = acc;
        acc += c;
    }
    if (t == 255) g_boff[BATCH * NBIN] = acc;
}

__global__ void bin_scatter(const float* __restrict__ pos) {
    int i = blockIdx.x * 256 + threadIdx.x;
    int b = i >> 12, n = i & 4095;
    const float* p = pos + (b * NPTS + n) * 3;
    float x = p[0], y = p[1], z = p[2];
    int bx = bin_of(x), by = bin_of(y), bz = bin_of(z);
    int pn_bin = b * NBIN + (bx * 16 + by) * 16 + bz;
    int slot = atomicAdd(&g_bcur[pn_bin], 1);
    float pn = __fadd_rn(__fadd_rn(__fmul_rn(x, x), __fmul_rn(y, y)), __fmul_rn(z, z));
    g_pts[slot] = make_float4(x, y, z, pn);
    g_pidx[slot] = n;
}

// ---------------- KNN: one thread per voxel, expanding Chebyshev shells ----
// d bit-matches reference: d = (gn + pn) - 2*fma(gz,pz,fma(gy,py,mul(gx,px))).
// Full lexicographic (d, idx) insert -> result independent of scatter order.
// Stop bound: unscanned bins (Cheb >= r+1) have true dist >= r*h; formula-d
// differs from true d^2 by <~1e-6, margin 4e-5 covers it.
__global__ void knn_search(const float* __restrict__ pos) {
    int b = blockIdx.y;
    int g = blockIdx.x * 128 + threadIdx.x;
    int ix = g >> 8, iy = (g >> 4) & 15, iz = g & 15;
    float gx = grid_coord(ix), gy = grid_coord(iy), gz = grid_coord(iz);
    float gn = __fadd_rn(__fadd_rn(__fmul_rn(gx, gx), __fmul_rn(gy, gy)), __fmul_rn(gz, gz));

    float bd[KN]; int bi[KN];
#pragma unroll
    for (int j = 0; j < KN; j++) { bd[j] = 3e38f; bi[j] = 0x7fffffff; }

    int binbase = b * NBIN;
    for (int r = 0; r <= 15; r++) {
        for (int dz = -r; dz <= r; dz++) {
            int zz = iz + dz; if (zz < 0 || zz > 15) continue;
            bool zf = (dz == -r) || (dz == r);
            for (int dy = -r; dy <= r; dy++) {
                int yy = iy + dy; if (yy < 0 || yy > 15) continue;
                bool yf = (dy == -r) || (dy == r);
                int step = (zf || yf || r == 0) ? 1 : 2 * r;
                for (int dx = -r; dx <= r; dx += step) {
                    int xx = ix + dx; if (xx < 0 || xx > 15) continue;
                    int bin = binbase + (xx * 16 + yy) * 16 + zz;
                    int s = g_boff[bin], e = g_boff[bin + 1];
                    for (int j = s; j < e; j++) {
                        float4 p = g_pts[j];
                        float ee = fmaf(gz, p.z, fmaf(gy, p.y, __fmul_rn(gx, p.x)));
                        float d = __fsub_rn(__fadd_rn(gn, p.w), __fmul_rn(2.0f, ee));
                        int ii = g_pidx[j];
                        if (d < bd[KN - 1] || (d == bd[KN - 1] && ii < bi[KN - 1])) {
                            bool pr[KN];
#pragma unroll
                            for (int q = 0; q < KN; q++)
                                pr[q] = (d < bd[q]) || (d == bd[q] && ii < bi[q]);
#pragma unroll
                            for (int q = KN - 1; q >= 1; q--) {
                                bd[q] = pr[q - 1] ? bd[q - 1] : (pr[q] ? d : bd[q]);
                                bi[q] = pr[q - 1] ? bi[q - 1] : (pr[q] ? ii : bi[q]);
                            }
                            if (pr[0]) { bd[0] = d; bi[0] = ii; }
                        }
                    }
                }
            }
        }
        if (bd[KN - 1] < 1e37f) {
            float rb = 0.125f * (float)r;
            if (bd[KN - 1] + 4e-5f < rb * rb) break;
        }
    }
#pragma unroll
    for (int j = 0; j < KN; j++) g_knn[(b * GG + g) * KN + j] = bi[j];
}

// ---------------- Edge (BipartiteConv + update net): warp per voxel --------
__global__ void edge_kernel(const float* __restrict__ pos, const float* __restrict__ xin,
                            const float* __restrict__ pe_w1, const float* __restrict__ pe_b1,
                            const float* __restrict__ pe_w2, const float* __restrict__ pe_b2,
                            const float* __restrict__ f_w, const float* __restrict__ f_b,
                            const float* __restrict__ up_w, const float* __restrict__ up_b) {
    __shared__ __align__(16) float s_w2[HID * HID];
    __shared__ __align__(16) float s_up[HID * HID];
    __shared__ float s_pw1[3 * HID], s_pb1[HID], s_pb2[HID], s_fw[3 * HID], s_fb[HID], s_ub[HID];
    __shared__ __align__(16) float s_h1[8][KN][HID];
    __shared__ __align__(16) float s_agg[8][HID];

    int t = threadIdx.x;
    for (int i = t; i < HID * HID; i += 256) { s_w2[i] = pe_w2[i]; s_up[i] = up_w[i]; }
    if (t < 192) { s_pw1[t] = pe_w1[t]; s_fw[t] = f_w[t]; }
    if (t < 64)  { s_pb1[t] = pe_b1[t]; s_pb2[t] = pe_b2[t]; s_fb[t] = f_b[t]; s_ub[t] = up_b[t]; }
    __syncthreads();

    int warp = t >> 5, lane = t & 31;
    int b = blockIdx.y;
    int g = blockIdx.x * 8 + warp;
    float gx = grid_coord(g >> 8);
    float gy = grid_coord((g >> 4) & 15);
    float gz = grid_coord(g & 15);

    int o0 = 2 * lane, o1 = o0 + 1;
    float fm0[KN], fm1[KN];

#pragma unroll
    for (int k = 0; k < KN; k++) {
        int nidx = g_knn[(b * GG + g) * KN + k];
        const float* pp = pos + (b * NPTS + nidx) * 3;
        float rx = pp[0] - gx, ry = pp[1] - gy, rz = pp[2] - gz;
        const float* xp = xin + (b * NPTS + nidx) * 3;
        float f0 = xp[0], f1 = xp[1], f2 = xp[2];

        float h0 = s_pb1[o0] + rx * s_pw1[o0] + ry * s_pw1[64 + o0] + rz * s_pw1[128 + o0];
        float h1 = s_pb1[o1] + rx * s_pw1[o1] + ry * s_pw1[64 + o1] + rz * s_pw1[128 + o1];
        s_h1[warp][k][o0] = gelu_f(h0);
        s_h1[warp][k][o1] = gelu_f(h1);

        fm0[k] = s_fb[o0] + f0 * s_fw[o0] + f1 * s_fw[64 + o0] + f2 * s_fw[128 + o0];
        fm1[k] = s_fb[o1] + f0 * s_fw[o1] + f1 * s_fw[64 + o1] + f2 * s_fw[128 + o1];
    }
    __syncwarp();

    float a0 = 0.0f, a1 = 0.0f;
    for (int k = 0; k < KN; k++) {
        u64 pe01 = pack2(s_pb2[o0], s_pb2[o1]);
#pragma unroll
        for (int c = 0; c < HID; c += 4) {
            float4 av = *(const float4*)&s_h1[warp][k][c];
            u64 w0 = *(const u64*)&s_w2[(c + 0) * HID + o0];
            u64 w1 = *(const u64*)&s_w2[(c + 1) * HID + o0];
            u64 w2 = *(const u64*)&s_w2[(c + 2) * HID + o0];
            u64 w3 = *(const u64*)&s_w2[(c + 3) * HID + o0];
            ffma2(pe01, pack2(av.x, av.x), w0);
            ffma2(pe01, pack2(av.y, av.y), w1);
            ffma2(pe01, pack2(av.z, av.z), w2);
            ffma2(pe01, pack2(av.w, av.w), w3);
        }
        float pe0, pe1; unpack2(pe0, pe1, pe01);
        a0 = fmaf(pe0, fm0[k], a0);
        a1 = fmaf(pe1, fm1[k], a1);
    }
    a0 *= (1.0f / KN);
    a1 *= (1.0f / KN);
    s_agg[warp][o0] = a0;
    s_agg[warp][o1] = a1;
    __syncwarp();

    u64 u01 = pack2(s_ub[o0], s_ub[o1]);
#pragma unroll
    for (int c = 0; c < HID; c += 4) {
        float4 av = *(const float4*)&s_agg[warp][c];
        u64 w0 = *(const u64*)&s_up[(c + 0) * HID + o0];
        u64 w1 = *(const u64*)&s_up[(c + 1) * HID + o0];
        u64 w2 = *(const u64*)&s_up[(c + 2) * HID + o0];
        u64 w3 = *(const u64*)&s_up[(c + 3) * HID + o0];
        ffma2(u01, pack2(av.x, av.x), w0);
        ffma2(u01, pack2(av.y, av.y), w1);
        ffma2(u01, pack2(av.z, av.z), w2);
        ffma2(u01, pack2(av.w, av.w), w3);
    }
    float u0, u1; unpack2(u0, u1, u01);
    u0 = gelu_f(u0);
    u1 = gelu_f(u1);

    int iz = g & 15, iy = (g >> 4) & 15, ix = g >> 8;
    int sp = iz * 256 + iy * 16 + ix;
    g_vol[(b * HID + o0) * GG + sp] = u0;
    g_vol[(b * HID + o1) * GG + sp] = u1;
}

// ---------------- direct 3x3x3 conv, SAME, 64->64 ----------------
// XP x-outputs per thread, OG channels, LDS128 weight loads, fused BN prologue
// (from partials) and fused partial-stats epilogue.
template <int DIM, int CI, int OG, int XP, bool BNRELU>
__global__ void conv_kernel(const float* __restrict__ in, const float* __restrict__ w,
                            const float* __restrict__ bias, float* __restrict__ out,
                            int npart, float inv_n) {
    constexpr int P = DIM + 2;
    constexpr int XT = DIM / XP;
    constexpr int NT = DIM * XT;
    constexpr int NW = NT / 32;
    __shared__ float s_in[3 * CI * P * P];
    __shared__ __align__(16) float s_w[27 * CI * OG];
    __shared__ float s_mean[HID], s_inv[HID];
    __shared__ float sred_s[NW][OG], sred_q[NW][OG];

    int z = blockIdx.x, b = blockIdx.y, o0 = blockIdx.z * OG;
    int t = threadIdx.x;
    int y = t / XT, xp = t % XT;

    if (BNRELU) {
        for (int c = t; c < HID; c += NT) {
            float S = 0.0f, Q = 0.0f;
            for (int p = 0; p < npart; p++) { S += g_ps[p * HID + c]; Q += g_pq[p * HID + c]; }
            float m = S * inv_n;
            s_mean[c] = m;
            s_inv[c] = rsqrtf(Q * inv_n - m * m + 1e-5f);
        }
        __syncthreads();
    }

    u64 accP[XP][OG / 2];
#pragma unroll
    for (int u = 0; u < XP; u++)
#pragma unroll
        for (int q = 0; q < OG / 2; q++)
            accP[u][q] = pack2(bias[o0 + 2 * q], bias[o0 + 2 * q + 1]);

    for (int cc = 0; cc < HID; cc += CI) {
        __syncthreads();
        for (int i = t; i < 3 * CI * P * P; i += NT) {
            int xx = i % P; int r = i / P; int yy = r % P; r /= P;
            int ci = r % CI; int pz = r / CI;
            int gz_ = z + pz - 1, gy_ = yy - 1, gx_ = xx - 1;
            float v = 0.0f;
            if (gz_ >= 0 && gz_ < DIM && gy_ >= 0 && gy_ < DIM && gx_ >= 0 && gx_ < DIM) {
                v = in[(((b * HID + cc + ci) * DIM + gz_) * DIM + gy_) * DIM + gx_];
                if (BNRELU) v = fmaxf(0.0f, (v - s_mean[cc + ci]) * s_inv[cc + ci]);
            }
            s_in[i] = v;
        }
        for (int i = t; i < 27 * CI * OG; i += NT) {
            int og = i % OG; int r = i / OG; int ci = r % CI; int tap = r / CI;
            s_w[i] = w[((o0 + og) * HID + cc + ci) * 27 + tap];
        }
        __syncthreads();

#pragma unroll 1
        for (int tap = 0; tap < 27; tap++) {
            int kd = tap / 9, kh = (tap / 3) % 3, kw = tap % 3;
            const float* ap = &s_in[(kd * CI) * P * P + (y + kh) * P + kw];
            const ulonglong2* wp4 = (const ulonglong2*)&s_w[tap * CI * OG];
#pragma unroll
            for (int ci = 0; ci < CI; ci++) {
                u64 a2[XP];
#pragma unroll
                for (int u = 0; u < XP; u++) {
                    float a = ap[ci * P * P + xp + u * XT];
                    a2[u] = pack2(a, a);
                }
#pragma unroll
                for (int q = 0; q < OG / 4; q++) {
                    ulonglong2 wv = wp4[ci * (OG / 4) + q];
#pragma unroll
                    for (int u = 0; u < XP; u++) {
                        ffma2(accP[u][2 * q + 0], a2[u], wv.x);
                        ffma2(accP[u][2 * q + 1], a2[u], wv.y);
                    }
                }
            }
        }
    }

    float acc[XP][OG];
#pragma unroll
    for (int u = 0; u < XP; u++)
#pragma unroll
        for (int q = 0; q < OG / 2; q++)
            unpack2(acc[u][2 * q], acc[u][2 * q + 1], accP[u][q]);

    int spatial = DIM * DIM * DIM;
#pragma unroll
    for (int u = 0; u < XP; u++)
#pragma unroll
        for (int q = 0; q < OG; q++)
            out[(b * HID + o0 + q) * spatial + (z * DIM + y) * DIM + (xp + u * XT)] = acc[u][q];

    int warp = t >> 5, lane = t & 31;
#pragma unroll
    for (int q = 0; q < OG; q++) {
        float s = 0.0f, qq = 0.0f;
#pragma unroll
        for (int u = 0; u < XP; u++) { s += acc[u][q]; qq += acc[u][q] * acc[u][q]; }
#pragma unroll
        for (int off = 16; off; off >>= 1) {
            s += __shfl_xor_sync(0xffffffffu, s, off);
            qq += __shfl_xor_sync(0xffffffffu, qq, off);
        }
        if (lane == 0) { sred_s[warp][q] = s; sred_q[warp][q] = qq; }
    }
    __syncthreads();
    if (t < OG) {
        float S = 0.0f, Q = 0.0f;
#pragma unroll
        for (int wv = 0; wv < NW; wv++) { S += sred_s[wv][t]; Q += sred_q[wv][t]; }
        int pblk = blockIdx.x * BATCH + blockIdx.y;
        g_ps[pblk * HID + o0 + t] = S;
        g_pq[pblk * HID + o0 + t] = Q;
    }
}

// ---------------- block0: stats prologue + residual + relu + maxpool -------
__global__ void resid_pool_kernel(const float* __restrict__ vol, const float* __restrict__ t2) {
    __shared__ float sS[64], sQ[64], s_mi[2];
    int c = blockIdx.x, b = blockIdx.y, t = threadIdx.x;  // 512 threads
    if (t < 64) { sS[t] = g_ps[t * HID + c]; sQ[t] = g_pq[t * HID + c]; }
    __syncthreads();
    if (t == 0) {
        float S = 0.0f, Q = 0.0f;
        for (int j = 0; j < 64; j++) { S += sS[j]; Q += sQ[j]; }
        float m = S * (1.0f / 16384.0f);
        s_mi[0] = m;
        s_mi[1] = rsqrtf(Q * (1.0f / 16384.0f) - m * m + 1e-5f);
    }
    __syncthreads();
    float m = s_mi[0], iv = s_mi[1];
    int z = t >> 6, y = (t >> 3) & 7, x = t & 7;
    const float* vb = vol + (b * HID + c) * 4096;
    const float* tb = t2 + (b * HID + c) * 4096;
    float best = 0.0f;
#pragma unroll
    for (int dz = 0; dz < 2; dz++)
#pragma unroll
        for (int dy = 0; dy < 2; dy++)
#pragma unroll
            for (int dx = 0; dx < 2; dx++) {
                int idx = ((2 * z + dz) * 16 + 2 * y + dy) * 16 + 2 * x + dx;
                float v = fmaxf(0.0f, vb[idx] + (tb[idx] - m) * iv);
                best = fmaxf(best, v);
            }
    g_vol2[(b * HID + c) * 512 + t] = best;
}

// ---------------- block1: stats prologue + residual + relu + sums ----------
__global__ void resid_sum_kernel(const float* __restrict__ vol2, const float* __restrict__ t2) {
    __shared__ float sS[32], sQ[32], s_mi[2];
    int c = blockIdx.x, b = blockIdx.y, t = threadIdx.x;  // 512 threads
    if (t < 32) { sS[t] = g_ps[t * HID + c]; sQ[t] = g_pq[t * HID + c]; }
    __syncthreads();
    if (t == 0) {
        float S = 0.0f, Q = 0.0f;
        for (int j = 0; j < 32; j++) { S += sS[j]; Q += sQ[j]; }
        float m = S * (1.0f / 2048.0f);
        s_mi[0] = m;
        s_mi[1] = rsqrtf(Q * (1.0f / 2048.0f) - m * m + 1e-5f);
    }
    __syncthreads();
    float m = s_mi[0], iv = s_mi[1];
    float v = fmaxf(0.0f, vol2[(b * HID + c) * 512 + t] + (t2[(b * HID + c) * 512 + t] - m) * iv);
    float s = v, q = v * v;
#pragma unroll
    for (int off = 16; off; off >>= 1) {
        s += __shfl_xor_sync(0xffffffffu, s, off);
        q += __shfl_xor_sync(0xffffffffu, q, off);
    }
    __shared__ float ss[16], sq[16];
    int warp = t >> 5, lane = t & 31;
    if (lane == 0) { ss[warp] = s; sq[warp] = q; }
    __syncthreads();
    if (t == 0) {
        float S = 0.0f, Q = 0.0f;
        for (int j = 0; j < 16; j++) { S += ss[j]; Q += sq[j]; }
        g_sum_bc[b * HID + c] = S;
        g_ssq_bc[b * HID + c] = Q;
    }
}

// ---------------- final BN + affine + spatial mean + linear head ----------
__global__ void head_kernel(const float* __restrict__ on_g, const float* __restrict__ on_b,
                            const float* __restrict__ ro_w, const float* __restrict__ ro_b,
                            float* __restrict__ out) {
    __shared__ float pooled[BATCH][HID];
    int t = threadIdx.x;  // 64 threads
    if (t < HID) {
        float S = 0.0f, Q = 0.0f;
        for (int b = 0; b < BATCH; b++) { S += g_sum_bc[b * HID + t]; Q += g_ssq_bc[b * HID + t]; }
        float n = (float)(BATCH * 512);
        float m = S / n;
        float var = Q / n - m * m;
        float iv = rsqrtf(var + 1e-5f);
        for (int b = 0; b < BATCH; b++)
            pooled[b][t] = (g_sum_bc[b * HID + t] * (1.0f / 512.0f) - m) * iv * on_g[t] + on_b[t];
    }
    __syncthreads();
    if (t < 64) {
        int b = t >> 4, j = t & 15;
        float s = ro_b[j];
        for (int c = 0; c < HID; c++) s = fmaf(pooled[b][c], ro_w[c * 16 + j], s);
        out[b * 16 + j] = s;
    }
}

// ---------------- launch ----------------
extern "C" void kernel_launch(void* const* d_in, const int* in_sizes, int n_in,
                              void* d_out, int out_size) {
    const float* pos   = (const float*)d_in[0];
    const float* xin   = (const float*)d_in[1];
    const float* pe_w1 = (const float*)d_in[2];
    const float* pe_b1 = (const float*)d_in[3];
    const float* pe_w2 = (const float*)d_in[4];
    const float* pe_b2 = (const float*)d_in[5];
    const float* f_w   = (const float*)d_in[6];
    const float* f_b   = (const float*)d_in[7];
    const float* up_w  = (const float*)d_in[8];
    const float* up_b  = (const float*)d_in[9];
    const float* conv_w = (const float*)d_in[10];  // [2,2,64,64,3,3,3]
    const float* conv_b = (const float*)d_in[11];  // [2,2,64]
    const float* on_g  = (const float*)d_in[12];
    const float* on_b  = (const float*)d_in[13];
    const float* ro_w  = (const float*)d_in[14];
    const float* ro_b  = (const float*)d_in[15];
    float* out = (float*)d_out;

    float *t1, *t2, *vol, *vol2;
    int* bcnt;
    cudaGetSymbolAddress((void**)&t1, g_t1);
    cudaGetSymbolAddress((void**)&t2, g_t2);
    cudaGetSymbolAddress((void**)&vol, g_vol);
    cudaGetSymbolAddress((void**)&vol2, g_vol2);
    cudaGetSymbolAddress((void**)&bcnt, g_bcnt);

    const int WSTRIDE = HID * HID * 27;

    // KNN via spatial binning
    cudaMemsetAsync(bcnt, 0, BATCH * NBIN * sizeof(int));
    bin_count<<<64, 256>>>(pos);
    bin_scan<<<1, 256>>>();
    bin_scatter<<<64, 256>>>(pos);
    knn_search<<<dim3(32, BATCH), 128>>>(pos);

    edge_kernel<<<dim3(512, BATCH), 256>>>(pos, xin, pe_w1, pe_b1, pe_w2, pe_b2,
                                           f_w, f_b, up_w, up_b);

    // block 0 @ 16^3
    conv_kernel<16, 4, 16, 2, false><<<dim3(16, BATCH, 4), 128>>>(
        vol, conv_w + 0 * WSTRIDE, conv_b + 0 * HID, t1, 0, 0.0f);
    conv_kernel<16, 4, 16, 2, true><<<dim3(16, BATCH, 4), 128>>>(
        t1, conv_w + 1 * WSTRIDE, conv_b + 1 * HID, t2, 64, 1.0f / 16384.0f);
    resid_pool_kernel<<<dim3(64, BATCH), 512>>>(vol, t2);

    // block 1 @ 8^3
    conv_kernel<8, 8, 16, 1, false><<<dim3(8, BATCH, 4), 64>>>(
        vol2, conv_w + 2 * WSTRIDE, conv_b + 2 * HID, t1, 0, 0.0f);
    conv_kernel<8, 8, 16, 1, true><<<dim3(8, BATCH, 4), 64>>>(
        t1, conv_w + 3 * WSTRIDE, conv_b + 3 * HID, t2, 32, 1.0f / 2048.0f);
    resid_sum_kernel<<<dim3(64, BATCH), 512>>>(vol2, t2);

    head_kernel<<<1, 64>>>(on_g, on_b, ro_w, ro_b, out);
}

// round 12
// speedup vs baseline: 1.0201x; 1.0201x over previous
#include <cuda_runtime.h>
#include <math.h>

#define RR 16
#define GG 4096
#define KN 8
#define HID 64
#define BATCH 4
#define NPTS 4096
#define NBIN 4096   // 16^3 bins per batch

typedef unsigned long long u64;

// ---------------- device scratch (no allocations allowed) ----------------
__device__ int    g_knn[BATCH * GG * KN];
__device__ float  g_vol[BATCH * HID * GG];
__device__ float  g_t1[BATCH * HID * GG];
__device__ float  g_t2[BATCH * HID * GG];
__device__ float  g_vol2[BATCH * HID * 512];
__device__ float  g_ps[64 * HID];
__device__ float  g_pq[64 * HID];
__device__ float  g_sum_bc[BATCH * HID];
__device__ float  g_ssq_bc[BATCH * HID];
// KNN binning
__device__ int    g_bcnt[BATCH * NBIN];
__device__ int    g_boff[BATCH * NBIN + 1];
__device__ int    g_bcur[BATCH * NBIN];
__device__ float4 g_pts[BATCH * NPTS];   // x,y,z,pn  (CSR order)
__device__ int    g_pidx[BATCH * NPTS];  // point index within batch

// ---------------- packed fp32x2 helpers (sm_103a FFMA2) ----------------
__device__ __forceinline__ void ffma2(u64& d, u64 a, u64 b) {
    asm("fma.rn.f32x2 %0, %1, %2, %0;" : "+l"(d) : "l"(a), "l"(b));
}
__device__ __forceinline__ u64 pack2(float lo, float hi) {
    u64 r; asm("mov.b64 %0, {%1, %2};" : "=l"(r) : "f"(lo), "f"(hi)); return r;
}
__device__ __forceinline__ void unpack2(float& lo, float& hi, u64 v) {
    asm("mov.b64 {%0, %1}, %2;" : "=f"(lo), "=f"(hi) : "l"(v));
}

__device__ __forceinline__ float gelu_f(float v) {
    float a = 0.7978845608028654f * (v + 0.044715f * v * v * v);
    float t = 1.0f - __fdividef(2.0f, __expf(2.0f * a) + 1.0f);
    return 0.5f * v * (1.0f + t);
}

// linspace(-1,1,16) bit-exact: rn(-1 + rn(i * rn(2/15)))
__device__ __forceinline__ float grid_coord(int i) {
    const float delta = 2.0f / 15.0f;
    return __fadd_rn(-1.0f, __fmul_rn((float)i, delta));
}

__device__ __forceinline__ int bin_of(float v) {
    int q = (int)floorf((v + 1.0f) * 8.0f);
    return min(15, max(0, q));
}

// ---------------- binning: count / scan / scatter ----------------
__global__ void bin_count(const float* __restrict__ pos) {
    int i = blockIdx.x * 256 + threadIdx.x;           // 16384 points
    int b = i >> 12, n = i & 4095;
    const float* p = pos + (b * NPTS + n) * 3;
    int bx = bin_of(p[0]), by = bin_of(p[1]), bz = bin_of(p[2]);
    atomicAdd(&g_bcnt[b * NBIN + (bx * 16 + by) * 16 + bz], 1);
}

__global__ void bin_scan() {   // 1 block, 256 threads, 16384 bins
    __shared__ int ssum[256];
    __shared__ int spre[256];
    int t = threadIdx.x;
    int base = t * 64;
    int s = 0;
    for (int k = 0; k < 64; k++) s += g_bcnt[base + k];
    ssum[t] = s;
    __syncthreads();
    if (t == 0) {
        int acc = 0;
        for (int k = 0; k < 256; k++) { spre[k] = acc; acc += ssum[k]; }
    }
    __syncthreads();
    int acc = spre[t];
    for (int k = 0; k < 64; k++) {
        int c = g_bcnt[base + k];
        g_boff[base + k] = acc;
        g_bcur[base + k] = acc;
        acc += c;
    }
    if (t == 255) g_boff[BATCH * NBIN] = acc;
}

__global__ void bin_scatter(const float* __restrict__ pos) {
    int i = blockIdx.x * 256 + threadIdx.x;
    int b = i >> 12, n = i & 4095;
    const float* p = pos + (b * NPTS + n) * 3;
    float x = p[0], y = p[1], z = p[2];
    int bx = bin_of(x), by = bin_of(y), bz = bin_of(z);
    int pn_bin = b * NBIN + (bx * 16 + by) * 16 + bz;
    int slot = atomicAdd(&g_bcur[pn_bin], 1);
    float pn = __fadd_rn(__fadd_rn(__fmul_rn(x, x), __fmul_rn(y, y)), __fmul_rn(z, z));
    g_pts[slot] = make_float4(x, y, z, pn);
    g_pidx[slot] = n;
}

// ---------------- KNN: WARP per voxel, lanes parallel over shell bins ------
// d bit-matches reference: d = (gn + pn) - 2*fma(gz,pz,fma(gy,py,mul(gx,px))).
// Per-lane sorted top-8 with full lexicographic (d, idx) insert (immune to the
// nondeterministic scatter order). After each shell r >= 2: non-destructive
// warp merge writes the current global top-8 (last write wins) and yields d8;
// stop when d8 + 4e-5 < (r*0.125)^2 (bins at Cheb >= r+1 have true dist >= r*h;
// margin covers the <=1e-6 formula-vs-true slop, so no reference-visible point
// can be excluded and no tie with d8 is possible).
__global__ void knn_search() {
    int b = blockIdx.y;
    int warp = threadIdx.x >> 5, lane = threadIdx.x & 31;
    int g = blockIdx.x * 8 + warp;
    int ix = g >> 8, iy = (g >> 4) & 15, iz = g & 15;
    float gx = grid_coord(ix), gy = grid_coord(iy), gz = grid_coord(iz);
    float gn = __fadd_rn(__fadd_rn(__fmul_rn(gx, gx), __fmul_rn(gy, gy)), __fmul_rn(gz, gz));

    float bd[KN]; int bi[KN];
#pragma unroll
    for (int j = 0; j < KN; j++) { bd[j] = 3e38f; bi[j] = 0x7fffffff; }

    int binbase = b * NBIN;
    int knn_out = (b * GG + g) * KN;

    for (int r = 0; r <= 15; r++) {
        int side = 2 * r + 1;
        int tot = side * side * side;
        for (int i = lane; i < tot; i += 32) {
            int dz = i / (side * side) - r;
            int rem = i % (side * side);
            int dy = rem / side - r;
            int dx = rem - (rem / side) * side - r;
            int cheb = max(abs(dx), max(abs(dy), abs(dz)));
            if (cheb != r) continue;                       // interior already scanned
            int xx = ix + dx, yy = iy + dy, zz = iz + dz;
            if ((unsigned)xx > 15u || (unsigned)yy > 15u || (unsigned)zz > 15u) continue;
            int bin = binbase + (xx * 16 + yy) * 16 + zz;
            int s = g_boff[bin], e = g_boff[bin + 1];
            for (int j = s; j < e; j++) {
                float4 p = g_pts[j];
                int ii = g_pidx[j];
                float ee = fmaf(gz, p.z, fmaf(gy, p.y, __fmul_rn(gx, p.x)));
                float d = __fsub_rn(__fadd_rn(gn, p.w), __fmul_rn(2.0f, ee));
                if (d < bd[KN - 1] || (d == bd[KN - 1] && ii < bi[KN - 1])) {
                    bool pr[KN];
#pragma unroll
                    for (int q = 0; q < KN; q++)
                        pr[q] = (d < bd[q]) || (d == bd[q] && ii < bi[q]);
#pragma unroll
                    for (int q = KN - 1; q >= 1; q--) {
                        bd[q] = pr[q - 1] ? bd[q - 1] : (pr[q] ? d : bd[q]);
                        bi[q] = pr[q - 1] ? bi[q - 1] : (pr[q] ? ii : bi[q]);
                    }
                    if (pr[0]) { bd[0] = d; bi[0] = ii; }
                }
            }
        }

        if (r >= 2) {
            // non-destructive merged extraction: writes candidate top-8, yields d8
            float td[KN]; int ti[KN];
#pragma unroll
            for (int j = 0; j < KN; j++) { td[j] = bd[j]; ti[j] = bi[j]; }
            float d8 = 3e38f;
            for (int sel = 0; sel < KN; sel++) {
                float v = td[0]; int vi = ti[0]; int vl = lane;
#pragma unroll
                for (int off = 16; off; off >>= 1) {
                    float ov = __shfl_xor_sync(0xffffffffu, v, off);
                    int   oi = __shfl_xor_sync(0xffffffffu, vi, off);
                    int   ol = __shfl_xor_sync(0xffffffffu, vl, off);
                    if (ov < v || (ov == v && oi < vi)) { v = ov; vi = oi; vl = ol; }
                }
                if (lane == 0) g_knn[knn_out + sel] = vi;
                if (lane == vl) {
#pragma unroll
                    for (int j = 0; j < KN - 1; j++) { td[j] = td[j + 1]; ti[j] = ti[j + 1]; }
                    td[KN - 1] = 3e38f; ti[KN - 1] = 0x7fffffff;
                }
                d8 = v;
            }
            if (d8 < 1e37f) {
                float rb = 0.125f * (float)r;
                if (d8 + 4e-5f < rb * rb) break;
            }
        }
    }
}

// ---------------- Edge (BipartiteConv + update net): warp per voxel --------
__global__ void edge_kernel(const float* __restrict__ pos, const float* __restrict__ xin,
                            const float* __restrict__ pe_w1, const float* __restrict__ pe_b1,
                            const float* __restrict__ pe_w2, const float* __restrict__ pe_b2,
                            const float* __restrict__ f_w, const float* __restrict__ f_b,
                            const float* __restrict__ up_w, const float* __restrict__ up_b) {
    __shared__ __align__(16) float s_w2[HID * HID];
    __shared__ __align__(16) float s_up[HID * HID];
    __shared__ float s_pw1[3 * HID], s_pb1[HID], s_pb2[HID], s_fw[3 * HID], s_fb[HID], s_ub[HID];
    __shared__ __align__(16) float s_h1[8][KN][HID];
    __shared__ __align__(16) float s_agg[8][HID];

    int t = threadIdx.x;
    for (int i = t; i < HID * HID; i += 256) { s_w2[i] = pe_w2[i]; s_up[i] = up_w[i]; }
    if (t < 192) { s_pw1[t] = pe_w1[t]; s_fw[t] = f_w[t]; }
    if (t < 64)  { s_pb1[t] = pe_b1[t]; s_pb2[t] = pe_b2[t]; s_fb[t] = f_b[t]; s_ub[t] = up_b[t]; }
    __syncthreads();

    int warp = t >> 5, lane = t & 31;
    int b = blockIdx.y;
    int g = blockIdx.x * 8 + warp;
    float gx = grid_coord(g >> 8);
    float gy = grid_coord((g >> 4) & 15);
    float gz = grid_coord(g & 15);

    int o0 = 2 * lane, o1 = o0 + 1;
    float fm0[KN], fm1[KN];

#pragma unroll
    for (int k = 0; k < KN; k++) {
        int nidx = g_knn[(b * GG + g) * KN + k];
        const float* pp = pos + (b * NPTS + nidx) * 3;
        float rx = pp[0] - gx, ry = pp[1] - gy, rz = pp[2] - gz;
        const float* xp = xin + (b * NPTS + nidx) * 3;
        float f0 = xp[0], f1 = xp[1], f2 = xp[2];

        float h0 = s_pb1[o0] + rx * s_pw1[o0] + ry * s_pw1[64 + o0] + rz * s_pw1[128 + o0];
        float h1 = s_pb1[o1] + rx * s_pw1[o1] + ry * s_pw1[64 + o1] + rz * s_pw1[128 + o1];
        s_h1[warp][k][o0] = gelu_f(h0);
        s_h1[warp][k][o1] = gelu_f(h1);

        fm0[k] = s_fb[o0] + f0 * s_fw[o0] + f1 * s_fw[64 + o0] + f2 * s_fw[128 + o0];
        fm1[k] = s_fb[o1] + f0 * s_fw[o1] + f1 * s_fw[64 + o1] + f2 * s_fw[128 + o1];
    }
    __syncwarp();

    float a0 = 0.0f, a1 = 0.0f;
    for (int k = 0; k < KN; k++) {
        u64 pe01 = pack2(s_pb2[o0], s_pb2[o1]);
#pragma unroll
        for (int c = 0; c < HID; c += 4) {
            float4 av = *(const float4*)&s_h1[warp][k][c];
            u64 w0 = *(const u64*)&s_w2[(c + 0) * HID + o0];
            u64 w1 = *(const u64*)&s_w2[(c + 1) * HID + o0];
            u64 w2 = *(const u64*)&s_w2[(c + 2) * HID + o0];
            u64 w3 = *(const u64*)&s_w2[(c + 3) * HID + o0];
            ffma2(pe01, pack2(av.x, av.x), w0);
            ffma2(pe01, pack2(av.y, av.y), w1);
            ffma2(pe01, pack2(av.z, av.z), w2);
            ffma2(pe01, pack2(av.w, av.w), w3);
        }
        float pe0, pe1; unpack2(pe0, pe1, pe01);
        a0 = fmaf(pe0, fm0[k], a0);
        a1 = fmaf(pe1, fm1[k], a1);
    }
    a0 *= (1.0f / KN);
    a1 *= (1.0f / KN);
    s_agg[warp][o0] = a0;
    s_agg[warp][o1] = a1;
    __syncwarp();

    u64 u01 = pack2(s_ub[o0], s_ub[o1]);
#pragma unroll
    for (int c = 0; c < HID; c += 4) {
        float4 av = *(const float4*)&s_agg[warp][c];
        u64 w0 = *(const u64*)&s_up[(c + 0) * HID + o0];
        u64 w1 = *(const u64*)&s_up[(c + 1) * HID + o0];
        u64 w2 = *(const u64*)&s_up[(c + 2) * HID + o0];
        u64 w3 = *(const u64*)&s_up[(c + 3) * HID + o0];
        ffma2(u01, pack2(av.x, av.x), w0);
        ffma2(u01, pack2(av.y, av.y), w1);
        ffma2(u01, pack2(av.z, av.z), w2);
        ffma2(u01, pack2(av.w, av.w), w3);
    }
    float u0, u1; unpack2(u0, u1, u01);
    u0 = gelu_f(u0);
    u1 = gelu_f(u1);

    int iz = g & 15, iy = (g >> 4) & 15, ix = g >> 8;
    int sp = iz * 256 + iy * 16 + ix;
    g_vol[(b * HID + o0) * GG + sp] = u0;
    g_vol[(b * HID + o1) * GG + sp] = u1;
}

// ---------------- direct 3x3x3 conv, SAME, 64->64 ----------------
template <int DIM, int CI, int OG, int XP, bool BNRELU>
__global__ void conv_kernel(const float* __restrict__ in, const float* __restrict__ w,
                            const float* __restrict__ bias, float* __restrict__ out,
                            int npart, float inv_n) {
    constexpr int P = DIM + 2;
    constexpr int XT = DIM / XP;
    constexpr int NT = DIM * XT;
    constexpr int NW = NT / 32;
    __shared__ float s_in[3 * CI * P * P];
    __shared__ __align__(16) float s_w[27 * CI * OG];
    __shared__ float s_mean[HID], s_inv[HID];
    __shared__ float sred_s[NW][OG], sred_q[NW][OG];

    int z = blockIdx.x, b = blockIdx.y, o0 = blockIdx.z * OG;
    int t = threadIdx.x;
    int y = t / XT, xp = t % XT;

    if (BNRELU) {
        for (int c = t; c < HID; c += NT) {
            float S = 0.0f, Q = 0.0f;
            for (int p = 0; p < npart; p++) { S += g_ps[p * HID + c]; Q += g_pq[p * HID + c]; }
            float m = S * inv_n;
            s_mean[c] = m;
            s_inv[c] = rsqrtf(Q * inv_n - m * m + 1e-5f);
        }
        __syncthreads();
    }

    u64 accP[XP][OG / 2];
#pragma unroll
    for (int u = 0; u < XP; u++)
#pragma unroll
        for (int q = 0; q < OG / 2; q++)
            accP[u][q] = pack2(bias[o0 + 2 * q], bias[o0 + 2 * q + 1]);

    for (int cc = 0; cc < HID; cc += CI) {
        __syncthreads();
        for (int i = t; i < 3 * CI * P * P; i += NT) {
            int xx = i % P; int r = i / P; int yy = r % P; r /= P;
            int ci = r % CI; int pz = r / CI;
            int gz_ = z + pz - 1, gy_ = yy - 1, gx_ = xx - 1;
            float v = 0.0f;
            if (gz_ >= 0 && gz_ < DIM && gy_ >= 0 && gy_ < DIM && gx_ >= 0 && gx_ < DIM) {
                v = in[(((b * HID + cc + ci) * DIM + gz_) * DIM + gy_) * DIM + gx_];
                if (BNRELU) v = fmaxf(0.0f, (v - s_mean[cc + ci]) * s_inv[cc + ci]);
            }
            s_in[i] = v;
        }
        for (int i = t; i < 27 * CI * OG; i += NT) {
            int og = i % OG; int r = i / OG; int ci = r % CI; int tap = r / CI;
            s_w[i] = w[((o0 + og) * HID + cc + ci) * 27 + tap];
        }
        __syncthreads();

#pragma unroll 1
        for (int tap = 0; tap < 27; tap++) {
            int kd = tap / 9, kh = (tap / 3) % 3, kw = tap % 3;
            const float* ap = &s_in[(kd * CI) * P * P + (y + kh) * P + kw];
            const ulonglong2* wp4 = (const ulonglong2*)&s_w[tap * CI * OG];
#pragma unroll
            for (int ci = 0; ci < CI; ci++) {
                u64 a2[XP];
#pragma unroll
                for (int u = 0; u < XP; u++) {
                    float a = ap[ci * P * P + xp + u * XT];
                    a2[u] = pack2(a, a);
                }
#pragma unroll
                for (int q = 0; q < OG / 4; q++) {
                    ulonglong2 wv = wp4[ci * (OG / 4) + q];
#pragma unroll
                    for (int u = 0; u < XP; u++) {
                        ffma2(accP[u][2 * q + 0], a2[u], wv.x);
                        ffma2(accP[u][2 * q + 1], a2[u], wv.y);
                    }
                }
            }
        }
    }

    float acc[XP][OG];
#pragma unroll
    for (int u = 0; u < XP; u++)
#pragma unroll
        for (int q = 0; q < OG / 2; q++)
            unpack2(acc[u][2 * q], acc[u][2 * q + 1], accP[u][q]);

    int spatial = DIM * DIM * DIM;
#pragma unroll
    for (int u = 0; u < XP; u++)
#pragma unroll
        for (int q = 0; q < OG; q++)
            out[(b * HID + o0 + q) * spatial + (z * DIM + y) * DIM + (xp + u * XT)] = acc[u][q];

    int warp = t >> 5, lane = t & 31;
#pragma unroll
    for (int q = 0; q < OG; q++) {
        float s = 0.0f, qq = 0.0f;
#pragma unroll
        for (int u = 0; u < XP; u++) { s += acc[u][q]; qq += acc[u][q] * acc[u][q]; }
#pragma unroll
        for (int off = 16; off; off >>= 1) {
            s += __shfl_xor_sync(0xffffffffu, s, off);
            qq += __shfl_xor_sync(0xffffffffu, qq, off);
        }
        if (lane == 0) { sred_s[warp][q] = s; sred_q[warp][q] = qq; }
    }
    __syncthreads();
    if (t < OG) {
        float S = 0.0f, Q = 0.0f;
#pragma unroll
        for (int wv = 0; wv < NW; wv++) { S += sred_s[wv][t]; Q += sred_q[wv][t]; }
        int pblk = blockIdx.x * BATCH + blockIdx.y;
        g_ps[pblk * HID + o0 + t] = S;
        g_pq[pblk * HID + o0 + t] = Q;
    }
}

// ---------------- block0: stats prologue + residual + relu + maxpool -------
__global__ void resid_pool_kernel(const float* __restrict__ vol, const float* __restrict__ t2) {
    __shared__ float sS[64], sQ[64], s_mi[2];
    int c = blockIdx.x, b = blockIdx.y, t = threadIdx.x;  // 512 threads
    if (t < 64) { sS[t] = g_ps[t * HID + c]; sQ[t] = g_pq[t * HID + c]; }
    __syncthreads();
    if (t == 0) {
        float S = 0.0f, Q = 0.0f;
        for (int j = 0; j < 64; j++) { S += sS[j]; Q += sQ[j]; }
        float m = S * (1.0f / 16384.0f);
        s_mi[0] = m;
        s_mi[1] = rsqrtf(Q * (1.0f / 16384.0f) - m * m + 1e-5f);
    }
    __syncthreads();
    float m = s_mi[0], iv = s_mi[1];
    int z = t >> 6, y = (t >> 3) & 7, x = t & 7;
    const float* vb = vol + (b * HID + c) * 4096;
    const float* tb = t2 + (b * HID + c) * 4096;
    float best = 0.0f;
#pragma unroll
    for (int dz = 0; dz < 2; dz++)
#pragma unroll
        for (int dy = 0; dy < 2; dy++)
#pragma unroll
            for (int dx = 0; dx < 2; dx++) {
                int idx = ((2 * z + dz) * 16 + 2 * y + dy) * 16 + 2 * x + dx;
                float v = fmaxf(0.0f, vb[idx] + (tb[idx] - m) * iv);
                best = fmaxf(best, v);
            }
    g_vol2[(b * HID + c) * 512 + t] = best;
}

// ---------------- block1: stats prologue + residual + relu + sums ----------
__global__ void resid_sum_kernel(const float* __restrict__ vol2, const float* __restrict__ t2) {
    __shared__ float sS[32], sQ[32], s_mi[2];
    int c = blockIdx.x, b = blockIdx.y, t = threadIdx.x;  // 512 threads
    if (t < 32) { sS[t] = g_ps[t * HID + c]; sQ[t] = g_pq[t * HID + c]; }
    __syncthreads();
    if (t == 0) {
        float S = 0.0f, Q = 0.0f;
        for (int j = 0; j < 32; j++) { S += sS[j]; Q += sQ[j]; }
        float m = S * (1.0f / 2048.0f);
        s_mi[0] = m;
        s_mi[1] = rsqrtf(Q * (1.0f / 2048.0f) - m * m + 1e-5f);
    }
    __syncthreads();
    float m = s_mi[0], iv = s_mi[1];
    float v = fmaxf(0.0f, vol2[(b * HID + c) * 512 + t] + (t2[(b * HID + c) * 512 + t] - m) * iv);
    float s = v, q = v * v;
#pragma unroll
    for (int off = 16; off; off >>= 1) {
        s += __shfl_xor_sync(0xffffffffu, s, off);
        q += __shfl_xor_sync(0xffffffffu, q, off);
    }
    __shared__ float ss[16], sq[16];
    int warp = t >> 5, lane = t & 31;
    if (lane == 0) { ss[warp] = s; sq[warp] = q; }
    __syncthreads();
    if (t == 0) {
        float S = 0.0f, Q = 0.0f;
        for (int j = 0; j < 16; j++) { S += ss[j]; Q += sq[j]; }
        g_sum_bc[b * HID + c] = S;
        g_ssq_bc[b * HID + c] = Q;
    }
}

// ---------------- final BN + affine + spatial mean + linear head ----------
__global__ void head_kernel(const float* __restrict__ on_g, const float* __restrict__ on_b,
                            const float* __restrict__ ro_w, const float* __restrict__ ro_b,
                            float* __restrict__ out) {
    __shared__ float pooled[BATCH][HID];
    int t = threadIdx.x;  // 64 threads
    if (t < HID) {
        float S = 0.0f, Q = 0.0f;
        for (int b = 0; b < BATCH; b++) { S += g_sum_bc[b * HID + t]; Q += g_ssq_bc[b * HID + t]; }
        float n = (float)(BATCH * 512);
        float m = S / n;
        float var = Q / n - m * m;
        float iv = rsqrtf(var + 1e-5f);
        for (int b = 0; b < BATCH; b++)
            pooled[b][t] = (g_sum_bc[b * HID + t] * (1.0f / 512.0f) - m) * iv * on_g[t] + on_b[t];
    }
    __syncthreads();
    if (t < 64) {
        int b = t >> 4, j = t & 15;
        float s = ro_b[j];
        for (int c = 0; c < HID; c++) s = fmaf(pooled[b][c], ro_w[c * 16 + j], s);
        out[b * 16 + j] = s;
    }
}

// ---------------- launch ----------------
extern "C" void kernel_launch(void* const* d_in, const int* in_sizes, int n_in,
                              void* d_out, int out_size) {
    const float* pos   = (const float*)d_in[0];
    const float* xin   = (const float*)d_in[1];
    const float* pe_w1 = (const float*)d_in[2];
    const float* pe_b1 = (const float*)d_in[3];
    const float* pe_w2 = (const float*)d_in[4];
    const float* pe_b2 = (const float*)d_in[5];
    const float* f_w   = (const float*)d_in[6];
    const float* f_b   = (const float*)d_in[7];
    const float* up_w  = (const float*)d_in[8];
    const float* up_b  = (const float*)d_in[9];
    const float* conv_w = (const float*)d_in[10];  // [2,2,64,64,3,3,3]
    const float* conv_b = (const float*)d_in[11];  // [2,2,64]
    const float* on_g  = (const float*)d_in[12];
    const float* on_b  = (const float*)d_in[13];
    const float* ro_w  = (const float*)d_in[14];
    const float* ro_b  = (const float*)d_in[15];
    float* out = (float*)d_out;

    float *t1, *t2, *vol, *vol2;
    int* bcnt;
    cudaGetSymbolAddress((void**)&t1, g_t1);
    cudaGetSymbolAddress((void**)&t2, g_t2);
    cudaGetSymbolAddress((void**)&vol, g_vol);
    cudaGetSymbolAddress((void**)&vol2, g_vol2);
    cudaGetSymbolAddress((void**)&bcnt, g_bcnt);

    const int WSTRIDE = HID * HID * 27;

    // KNN via spatial binning, warp-per-voxel search
    cudaMemsetAsync(bcnt, 0, BATCH * NBIN * sizeof(int));
    bin_count<<<64, 256>>>(pos);
    bin_scan<<<1, 256>>>();
    bin_scatter<<<64, 256>>>(pos);
    knn_search<<<dim3(512, BATCH), 256>>>();

    edge_kernel<<<dim3(512, BATCH), 256>>>(pos, xin, pe_w1, pe_b1, pe_w2, pe_b2,
                                           f_w, f_b, up_w, up_b);

    // block 0 @ 16^3
    conv_kernel<16, 4, 16, 2, false><<<dim3(16, BATCH, 4), 128>>>(
        vol, conv_w + 0 * WSTRIDE, conv_b + 0 * HID, t1, 0, 0.0f);
    conv_kernel<16, 4, 16, 2, true><<<dim3(16, BATCH, 4), 128>>>(
        t1, conv_w + 1 * WSTRIDE, conv_b + 1 * HID, t2, 64, 1.0f / 16384.0f);
    resid_pool_kernel<<<dim3(64, BATCH), 512>>>(vol, t2);

    // block 1 @ 8^3
    conv_kernel<8, 8, 16, 1, false><<<dim3(8, BATCH, 4), 64>>>(
        vol2, conv_w + 2 * WSTRIDE, conv_b + 2 * HID, t1, 0, 0.0f);
    conv_kernel<8, 8, 16, 1, true><<<dim3(8, BATCH, 4), 64>>>(
        t1, conv_w + 3 * WSTRIDE, conv_b + 3 * HID, t2, 32, 1.0f / 2048.0f);
    resid_sum_kernel<<<dim3(64, BATCH), 512>>>(vol2, t2);

    head_kernel<<<1, 64>>>(on_g, on_b, ro_w, ro_b, out);
}